// round 1
// baseline (speedup 1.0000x reference)
#include <cuda_runtime.h>
#include <math.h>

// ---------------------------------------------------------------------------
// QuantPINN: 7x quant_linear MLP with per-tensor int8 fake quantization.
// Exact-integer strategy: xq @ wq.T = (sx*sw) * (Xint @ Wint^T), int8 dp4a GEMM.
// Per-layer global max reductions via atomicMax on float bits across launches.
// ---------------------------------------------------------------------------

#define N_MAX 262144
#define HID   100
#define KG    25          // 100 / 4 int8s per packed word
#define QMAXF 127.0f

// Ping-pong activation buffers (fp32, exact path)
__device__ float g_hA[N_MAX * HID];
__device__ float g_hB[N_MAX * HID];
// Packed int8 weights for hidden layers 2..6: [layer][kgroup][out-col padded to 104]
__device__ int   g_Wp[5][KG][104];
// Layer 1 integer weights [100][2]
__device__ int   g_W1i[HID * 2];
// Output layer packed weights [2][25]
__device__ int   g_Wpo[2][KG];
// Per-layer weight scales: 0=W1, 1..5=W2..W6, 6=Wout
__device__ float g_sw[7];
// Activation |max| slots as float bits: 0=input x, 1..6 = h1..h6
__device__ int   g_slots[8];

// ---------------------------------------------------------------------------

__device__ __forceinline__ float read_scale(int slot) {
    float m = __int_as_float(g_slots[slot]);
    float s = m / QMAXF;
    return fmaxf(s, 1e-12f);
}

__device__ __forceinline__ int q8(float v, float inv_scale) {
    float x = v * inv_scale;
    x = fminf(fmaxf(x, -127.0f), 127.0f);
    return __float2int_rn(x);   // round-to-nearest-even == jnp.round
}

__device__ __forceinline__ int pack4(int a, int b, int c, int d) {
    return (a & 0xFF) | ((b & 0xFF) << 8) | ((c & 0xFF) << 16) | ((d & 0xFF) << 24);
}

__device__ __forceinline__ float bias_q(float b, float sb) {
    // clip(round(b/sb), -128, 127) * sb
    float r = rintf(b / sb);
    r = fminf(fmaxf(r, -128.0f), 127.0f);
    return r * sb;
}

__device__ __forceinline__ void warp_max_atomic(float v, int slot) {
    #pragma unroll
    for (int off = 16; off > 0; off >>= 1)
        v = fmaxf(v, __shfl_xor_sync(0xffffffffu, v, off));
    if ((threadIdx.x & 31) == 0)
        atomicMax(&g_slots[slot], __float_as_int(v));  // v >= 0 -> bits monotone
}

// ---------------------------------------------------------------------------
// 0) zero the scale slots
__global__ void k_zero_slots() {
    if (threadIdx.x < 8) g_slots[threadIdx.x] = 0;
}

// 1) global max of |concat(z,t)|  -> slot 0
__global__ void k_input_max(const float* __restrict__ z, const float* __restrict__ t, int n) {
    float m = 0.0f;
    for (int i = blockIdx.x * blockDim.x + threadIdx.x; i < n; i += gridDim.x * blockDim.x)
        m = fmaxf(m, fmaxf(fabsf(z[i]), fabsf(t[i])));
    warp_max_atomic(m, 0);
}

// 2) per-layer weight quantization + packing. blockIdx.x = layer 0..6
__global__ void k_weight_prep(const float* __restrict__ W1,
                              const float* __restrict__ W2, const float* __restrict__ W3,
                              const float* __restrict__ W4, const float* __restrict__ W5,
                              const float* __restrict__ W6, const float* __restrict__ Wout) {
    int l = blockIdx.x;
    const float* W;
    int cnt;
    if (l == 0)      { W = W1;   cnt = HID * 2; }
    else if (l == 6) { W = Wout; cnt = 2 * HID; }
    else {
        const float* Ws_[5] = {W2, W3, W4, W5, W6};
        W = Ws_[l - 1]; cnt = HID * HID;
    }

    __shared__ float red[256];
    float m = 0.0f;
    for (int i = threadIdx.x; i < cnt; i += 256) m = fmaxf(m, fabsf(W[i]));
    red[threadIdx.x] = m;
    __syncthreads();
    for (int s = 128; s > 0; s >>= 1) {
        if (threadIdx.x < s) red[threadIdx.x] = fmaxf(red[threadIdx.x], red[threadIdx.x + s]);
        __syncthreads();
    }
    __shared__ float s_sw;
    if (threadIdx.x == 0) {
        float sw = fmaxf(red[0] / QMAXF, 1e-12f);
        g_sw[l] = sw;
        s_sw = sw;
    }
    __syncthreads();
    float inv = 1.0f / s_sw;

    if (l == 0) {
        for (int i = threadIdx.x; i < HID * 2; i += 256)
            g_W1i[i] = q8(W[i], inv);
    } else if (l == 6) {
        for (int w = threadIdx.x; w < 2 * KG; w += 256) {
            int o = w / KG, kg = w % KG;
            int base = o * HID + kg * 4;
            g_Wpo[o][kg] = pack4(q8(W[base + 0], inv), q8(W[base + 1], inv),
                                 q8(W[base + 2], inv), q8(W[base + 3], inv));
        }
    } else {
        for (int w = threadIdx.x; w < KG * 104; w += 256) {
            int kg = w / 104, c = w % 104;
            int p = 0;
            if (c < HID) {
                int base = c * HID + kg * 4;   // W row-major [out][in]
                p = pack4(q8(W[base + 0], inv), q8(W[base + 1], inv),
                          q8(W[base + 2], inv), q8(W[base + 3], inv));
            }
            g_Wp[l - 1][kg][c] = p;
        }
    }
}

// ---------------------------------------------------------------------------
// 3) layer 1: x=[z,t] (K=2) -> h1 [N,100], tanh, max -> slot 1
//    thread handles 4 consecutive outputs of one row -> coalesced float4 store
__global__ void k_layer1(const float* __restrict__ z, const float* __restrict__ t,
                         const float* __restrict__ b1, int n) {
    int idx = blockIdx.x * blockDim.x + threadIdx.x;
    int i  = idx / 25;
    int og = idx % 25;
    float vmax = 0.0f;
    if (i < n) {
        float sx = read_scale(0);
        float invsx = 1.0f / sx;
        int zi = q8(z[i], invsx);
        int ti = q8(t[i], invsx);
        float sw = g_sw[0];
        float sb = sx * sw;
        float4 hv;
        float* hp = &hv.x;
        #pragma unroll
        for (int j = 0; j < 4; j++) {
            int o = og * 4 + j;
            int acc = zi * g_W1i[o * 2] + ti * g_W1i[o * 2 + 1];
            float y = (float)acc * sb + bias_q(b1[o], sb);
            float h = tanhf(y);
            hp[j] = h;
            vmax = fmaxf(vmax, fabsf(h));
        }
        ((float4*)(g_hA + (size_t)i * HID))[og] = hv;
    }
    warp_max_atomic(vmax, 1);
}

// ---------------------------------------------------------------------------
// 4) hidden layer: quantize-in, int8 dp4a GEMM 128x100 (K=100), tanh, max.
//    416 threads = 13 warps; thread tile = 4 rows x 8 cols (out padded to 104).
__global__ void __launch_bounds__(416, 2)
k_hidden(const float* __restrict__ bias, int lidx, int dir, int n) {
    const float* hin  = dir ? g_hB : g_hA;
    float*       hout = dir ? g_hA : g_hB;

    __shared__ __align__(16) int Xs[KG][128];
    __shared__ __align__(16) int Ws[KG][104];
    __shared__ float bqs[104];

    int tid = threadIdx.x;
    size_t row0 = (size_t)blockIdx.x * 128;

    float sx = read_scale(lidx);          // slot_in == lidx (1..5)
    float invsx = 1.0f / sx;
    float sw = g_sw[lidx];
    float sb = sx * sw;

    // quantize input tile: 128 rows x 25 packed words
    const float4* src = (const float4*)(hin + row0 * HID);
    for (int w = tid; w < 128 * KG; w += 416) {
        int r = w / KG, kg = w % KG;
        int p = 0;
        if (row0 + (size_t)r < (size_t)n) {
            float4 v = src[r * KG + kg];
            p = pack4(q8(v.x, invsx), q8(v.y, invsx), q8(v.z, invsx), q8(v.w, invsx));
        }
        Xs[kg][r] = p;
    }
    // copy packed weights
    const int* wp = &g_Wp[lidx - 1][0][0];
    for (int w = tid; w < KG * 104; w += 416)
        ((int*)Ws)[w] = wp[w];
    // quantized bias
    if (tid < 104) {
        float bq = 0.0f;
        if (tid < HID) bq = bias_q(bias[tid], sb);
        bqs[tid] = bq;
    }
    __syncthreads();

    int cg = tid % 13, rg = tid / 13;
    int c0 = cg * 8, r0 = rg * 4;

    int acc[4][8];
    #pragma unroll
    for (int r = 0; r < 4; r++)
        #pragma unroll
        for (int c = 0; c < 8; c++) acc[r][c] = 0;

    for (int kg = 0; kg < KG; kg++) {
        int4 xv = *(const int4*)&Xs[kg][r0];
        int4 w0 = *(const int4*)&Ws[kg][c0];
        int4 w1 = *(const int4*)&Ws[kg][c0 + 4];
        int xr[4] = {xv.x, xv.y, xv.z, xv.w};
        int wr[8] = {w0.x, w0.y, w0.z, w0.w, w1.x, w1.y, w1.z, w1.w};
        #pragma unroll
        for (int r = 0; r < 4; r++)
            #pragma unroll
            for (int c = 0; c < 8; c++)
                acc[r][c] = __dp4a(xr[r], wr[c], acc[r][c]);
    }

    int nvalid = (c0 + 8 <= HID) ? 8 : 4;   // cg==12 -> cols 96..99 valid
    float vmax = 0.0f;
    #pragma unroll
    for (int r = 0; r < 4; r++) {
        size_t row = row0 + (size_t)(r0 + r);
        float o[8];
        #pragma unroll
        for (int c = 0; c < 8; c++) {
            float y = (float)acc[r][c] * sb + bqs[c0 + c];
            o[c] = tanhf(y);
        }
        if (row < (size_t)n) {
            #pragma unroll
            for (int c = 0; c < 8; c++)
                if (c < nvalid) vmax = fmaxf(vmax, fabsf(o[c]));
            float* dst = hout + row * HID + c0;
            float4 v0 = make_float4(o[0], o[1], o[2], o[3]);
            *(float4*)dst = v0;
            if (nvalid == 8) {
                float4 v1 = make_float4(o[4], o[5], o[6], o[7]);
                *(float4*)(dst + 4) = v1;
            }
        }
    }
    warp_max_atomic(vmax, lidx + 1);
}

// ---------------------------------------------------------------------------
// 5) output layer: [N,100] -> [N,2], no tanh. 64 rows per block.
__global__ void k_out(const float* __restrict__ bout, float* __restrict__ out,
                      int dir, int n) {
    const float* hin = dir ? g_hB : g_hA;
    __shared__ int Xs[KG][64];
    __shared__ float s_bq[2];

    int tid = threadIdx.x;
    size_t row0 = (size_t)blockIdx.x * 64;

    float sx = read_scale(6);
    float invsx = 1.0f / sx;
    float sw = g_sw[6];
    float sb = sx * sw;

    const float4* src = (const float4*)(hin + row0 * HID);
    for (int w = tid; w < 64 * KG; w += 256) {
        int r = w / KG, kg = w % KG;
        int p = 0;
        if (row0 + (size_t)r < (size_t)n) {
            float4 v = src[r * KG + kg];
            p = pack4(q8(v.x, invsx), q8(v.y, invsx), q8(v.z, invsx), q8(v.w, invsx));
        }
        Xs[kg][r] = p;
    }
    if (tid < 2) s_bq[tid] = bias_q(bout[tid], sb);
    __syncthreads();

    if (tid < 128) {
        int r = tid >> 1, o = tid & 1;
        size_t row = row0 + (size_t)r;
        if (row < (size_t)n) {
            int wv[KG];
            #pragma unroll
            for (int kg = 0; kg < KG; kg++) wv[kg] = g_Wpo[o][kg];
            int acc = 0;
            #pragma unroll
            for (int kg = 0; kg < KG; kg++)
                acc = __dp4a(Xs[kg][r], wv[kg], acc);
            out[row * 2 + o] = (float)acc * sb + s_bq[o];
        }
    }
}

// ---------------------------------------------------------------------------

extern "C" void kernel_launch(void* const* d_in, const int* in_sizes, int n_in,
                              void* d_out, int out_size) {
    const float* z    = (const float*)d_in[0];
    const float* t    = (const float*)d_in[1];
    const float* W1   = (const float*)d_in[2];
    const float* b1   = (const float*)d_in[3];
    const float* W2   = (const float*)d_in[4];
    const float* b2   = (const float*)d_in[5];
    const float* W3   = (const float*)d_in[6];
    const float* b3   = (const float*)d_in[7];
    const float* W4   = (const float*)d_in[8];
    const float* b4   = (const float*)d_in[9];
    const float* W5   = (const float*)d_in[10];
    const float* b5   = (const float*)d_in[11];
    const float* W6   = (const float*)d_in[12];
    const float* b6   = (const float*)d_in[13];
    const float* Wout = (const float*)d_in[14];
    const float* bout = (const float*)d_in[15];
    int n = in_sizes[0];

    k_zero_slots<<<1, 32>>>();
    k_input_max<<<256, 256>>>(z, t, n);
    k_weight_prep<<<7, 256>>>(W1, W2, W3, W4, W5, W6, Wout);

    int l1_blocks = (n * 25 + 255) / 256;
    k_layer1<<<l1_blocks, 256>>>(z, t, b1, n);

    int hblocks = (n + 127) / 128;
    k_hidden<<<hblocks, 416>>>(b2, 1, 0, n);   // A -> B
    k_hidden<<<hblocks, 416>>>(b3, 2, 1, n);   // B -> A
    k_hidden<<<hblocks, 416>>>(b4, 3, 0, n);   // A -> B
    k_hidden<<<hblocks, 416>>>(b5, 4, 1, n);   // B -> A
    k_hidden<<<hblocks, 416>>>(b6, 5, 0, n);   // A -> B

    int oblocks = (n + 63) / 64;
    k_out<<<oblocks, 256>>>(bout, (float*)d_out, 1, n);   // read B
}